// round 4
// baseline (speedup 1.0000x reference)
#include <cuda_runtime.h>
#include <math.h>

#define WFULL 0xffffffffu

// One warp per 64x64 SPD matrix. Each lane holds TWO full columns (its current
// Jacobi pair) in registers. One-sided Jacobi: orthogonalize columns of X by
// right rotations; columns converge to lambda_i * u_i.
// logm(X) = sum_i (0.5*log(d_ii)/d_ii) * g_i g_i^T  with d_ii = ||g_i||^2.
__global__ __launch_bounds__(64, 1)
void logeig_jacobi(const float* __restrict__ X, float* __restrict__ Out, int nmat)
{
    const int lane = threadIdx.x & 31;
    const int warp = threadIdx.x >> 5;
    const int mat  = blockIdx.x * 2 + warp;

    // per-warp: 64x64 column dump (row stride 68 floats, conflict-free) + 64 weights
    __shared__ float sh[2][64 * 68 + 64];

    if (mat >= nmat) return;

    const float* Xm = X + (size_t)mat * 4096;
    float*       Om = Out + (size_t)mat * 4096;

    float T[64];   // "top" column of this lane's current pair
    float Bv[64];  // "bot" column

    // Initial assignment: lane holds columns lane (top) and lane+32 (bot).
    // X symmetric -> column j == row j (contiguous, float4-aligned).
    {
        const float4* rT = reinterpret_cast<const float4*>(Xm + lane * 64);
        const float4* rB = reinterpret_cast<const float4*>(Xm + (lane + 32) * 64);
#pragma unroll
        for (int m = 0; m < 16; m++) {
            float4 a = rT[m];
            T[4*m+0] = a.x; T[4*m+1] = a.y; T[4*m+2] = a.z; T[4*m+3] = a.w;
            float4 b = rB[m];
            Bv[4*m+0] = b.x; Bv[4*m+1] = b.y; Bv[4*m+2] = b.z; Bv[4*m+3] = b.w;
        }
    }

    float dT = 0.0f, dB = 0.0f;  // cached squared norms of T / Bv

    for (int sweep = 0; sweep < 16; sweep++) {
        // Exact norm refresh at sweep start (kills incremental drift).
        {
            float a0=0.f,a1=0.f,a2=0.f,a3=0.f, b0=0.f,b1=0.f,b2=0.f,b3=0.f;
#pragma unroll
            for (int k = 0; k < 64; k += 4) {
                a0 = fmaf(T[k+0], T[k+0], a0);
                a1 = fmaf(T[k+1], T[k+1], a1);
                a2 = fmaf(T[k+2], T[k+2], a2);
                a3 = fmaf(T[k+3], T[k+3], a3);
                b0 = fmaf(Bv[k+0], Bv[k+0], b0);
                b1 = fmaf(Bv[k+1], Bv[k+1], b1);
                b2 = fmaf(Bv[k+2], Bv[k+2], b2);
                b3 = fmaf(Bv[k+3], Bv[k+3], b3);
            }
            dT = (a0+a1)+(a2+a3);
            dB = (b0+b1)+(b2+b3);
        }

        bool rot_any = false;

#pragma unroll 1
        for (int r = 0; r < 63; r++) {
            // Cross dot product of this lane's pair (fully local).
            float a0=0.f,a1=0.f,a2=0.f,a3=0.f;
#pragma unroll
            for (int k = 0; k < 64; k += 4) {
                a0 = fmaf(T[k+0], Bv[k+0], a0);
                a1 = fmaf(T[k+1], Bv[k+1], a1);
                a2 = fmaf(T[k+2], Bv[k+2], a2);
                a3 = fmaf(T[k+3], Bv[k+3], a3);
            }
            float dot = (a0+a1)+(a2+a3);

            if (dot*dot > 1e-14f * dT * dB) {
                // Annihilate Gram off-diagonal: tau=(dqq-dpp)/(2 dpq)
                float tau = (dB - dT) / (2.0f * dot);
                float tt  = 1.0f / (fabsf(tau) + sqrtf(fmaf(tau, tau, 1.0f)));
                tt = copysignf(tt, tau);
                float c = rsqrtf(fmaf(tt, tt, 1.0f));
                float s = tt * c;
#pragma unroll
                for (int k = 0; k < 64; k++) {
                    float tp = fmaf(c, T[k], -s * Bv[k]);
                    Bv[k]    = fmaf(s, T[k],  c * Bv[k]);
                    T[k]     = tp;
                }
                dT = fmaf(-tt, dot, dT);
                dB = fmaf( tt, dot, dB);
                rot_any = true;
            }

            // Round-robin caterpillar shift (top0 fixed):
            //  newT[0]=T[0]; newT[1]=B[0]; newT[i]=T[i-1];
            //  newB[i]=B[i+1]; newB[31]=T[31]
#pragma unroll
            for (int k = 0; k < 64; k++) {
                float sendT = (lane == 0) ? Bv[k] : T[k];
                float upT   = __shfl_up_sync(WFULL, sendT, 1);
                float dnB   = __shfl_down_sync(WFULL, Bv[k], 1);
                float nT = (lane == 0)  ? T[k] : upT;
                float nB = (lane == 31) ? T[k] : dnB;
                T[k]  = nT;
                Bv[k] = nB;
            }
            {   // cached norms travel with their columns
                float sendT = (lane == 0) ? dB : dT;
                float upT   = __shfl_up_sync(WFULL, sendT, 1);
                float dnB   = __shfl_down_sync(WFULL, dB, 1);
                float nT = (lane == 0)  ? dT : upT;
                float nB = (lane == 31) ? dT : dnB;
                dT = nT;
                dB = nB;
            }
        }
        // After 63 rounds the tournament is back at the initial placement,
        // so breaking here leaves column i on its home lane/slot.
        if (!__any_sync(WFULL, rot_any)) break;
    }

    // ---- Reconstruction: Out = sum_i w_i g_i g_i^T ----
    float* S = sh[warp];
    float* w = sh[warp] + 64 * 68;

    // Fresh final norms (exact eigenvalue^2).
    {
        float a0=0.f,a1=0.f,a2=0.f,a3=0.f, b0=0.f,b1=0.f,b2=0.f,b3=0.f;
#pragma unroll
        for (int k = 0; k < 64; k += 4) {
            a0 = fmaf(T[k+0], T[k+0], a0);
            a1 = fmaf(T[k+1], T[k+1], a1);
            a2 = fmaf(T[k+2], T[k+2], a2);
            a3 = fmaf(T[k+3], T[k+3], a3);
            b0 = fmaf(Bv[k+0], Bv[k+0], b0);
            b1 = fmaf(Bv[k+1], Bv[k+1], b1);
            b2 = fmaf(Bv[k+2], Bv[k+2], b2);
            b3 = fmaf(Bv[k+3], Bv[k+3], b3);
        }
        dT = (a0+a1)+(a2+a3);
        dB = (b0+b1)+(b2+b3);
    }

    // Dump columns element-major: S[k*68 + i] = g_i[k]   (conflict-free)
#pragma unroll
    for (int k = 0; k < 64; k++) S[k*68 + lane] = T[k];
#pragma unroll
    for (int k = 0; k < 64; k++) S[k*68 + lane + 32] = Bv[k];
    // w_i = log(lambda_i)/lambda_i^2 = 0.5*log(d_ii)/d_ii
    w[lane]      = 0.5f * logf(dT) / dT;
    w[lane + 32] = 0.5f * logf(dB) / dB;
    __syncwarp();

    // Lane computes output rows {lane, lane+32}.
    // av[i] = w_i * g_i[r0], bv[i] = w_i * g_i[r1]
    float av[64], bv[64];
#pragma unroll
    for (int i = 0; i < 64; i++) {
        float wi = w[i];
        av[i] = wi * S[lane*68 + i];
        bv[i] = wi * S[(lane + 32)*68 + i];
    }

#pragma unroll 1
    for (int c = 0; c < 64; c++) {
        const float* Sc = S + c*68;   // same for all lanes -> broadcast loads
        float s00=0.f,s01=0.f,s10=0.f,s11=0.f;
#pragma unroll
        for (int i = 0; i < 64; i += 2) {
            float g0 = Sc[i], g1 = Sc[i+1];
            s00 = fmaf(av[i],   g0, s00);
            s01 = fmaf(av[i+1], g1, s01);
            s10 = fmaf(bv[i],   g0, s10);
            s11 = fmaf(bv[i+1], g1, s11);
        }
        Om[lane*64 + c]        = s00 + s01;
        Om[(lane + 32)*64 + c] = s10 + s11;
    }
}

extern "C" void kernel_launch(void* const* d_in, const int* in_sizes, int n_in,
                              void* d_out, int out_size)
{
    const float* X  = (const float*)d_in[0];
    float*       Om = (float*)d_out;
    int nmat = in_sizes[0] / 4096;      // 8192 matrices of 64x64
    int blocks = (nmat + 1) / 2;        // 2 warps (2 matrices) per CTA
    logeig_jacobi<<<blocks, 64>>>(X, Om, nmat);
}

// round 5
// speedup vs baseline: 1.9120x; 1.9120x over previous
#include <cuda_runtime.h>
#include <math.h>

#define WFULL 0xffffffffu
typedef unsigned long long ull;

// ---- packed fp32x2 helpers (SASS FFMA2 path, ptxas won't emit from C++) ----
__device__ __forceinline__ float2 f2fma(float2 a, float2 b, float2 c) {
    float2 d;
    asm("fma.rn.f32x2 %0, %1, %2, %3;"
        : "=l"(reinterpret_cast<ull&>(d))
        : "l"(reinterpret_cast<ull&>(a)),
          "l"(reinterpret_cast<ull&>(b)),
          "l"(reinterpret_cast<ull&>(c)));
    return d;
}
__device__ __forceinline__ float2 f2mul(float2 a, float2 b) {
    float2 d;
    asm("mul.rn.f32x2 %0, %1, %2;"
        : "=l"(reinterpret_cast<ull&>(d))
        : "l"(reinterpret_cast<ull&>(a)),
          "l"(reinterpret_cast<ull&>(b)));
    return d;
}

// Jacobi rotation of this lane's local pair (A, B). Updates cached norms.
__device__ __forceinline__ void rotate_pair(float2 (&A)[32], float2 (&B)[32],
                                            float& da, float& db, bool& rot_any)
{
    float2 acc0 = {0.f,0.f}, acc1 = {0.f,0.f}, acc2 = {0.f,0.f}, acc3 = {0.f,0.f};
#pragma unroll
    for (int k = 0; k < 32; k += 4) {
        acc0 = f2fma(A[k],   B[k],   acc0);
        acc1 = f2fma(A[k+1], B[k+1], acc1);
        acc2 = f2fma(A[k+2], B[k+2], acc2);
        acc3 = f2fma(A[k+3], B[k+3], acc3);
    }
    float dot = ((acc0.x+acc0.y)+(acc1.x+acc1.y)) + ((acc2.x+acc2.y)+(acc3.x+acc3.y));

    if (dot*dot > 1e-10f * da * db) {
        float tau = (db - da) / (2.0f * dot);
        float tt  = 1.0f / (fabsf(tau) + sqrtf(fmaf(tau, tau, 1.0f)));
        tt = copysignf(tt, tau);
        float c = rsqrtf(fmaf(tt, tt, 1.0f));
        float s = tt * c;
        float2 c2 = {c,c}, s2 = {s,s}, ns2 = {-s,-s};
#pragma unroll
        for (int k = 0; k < 32; k++) {
            float2 a = A[k], b = B[k];
            A[k] = f2fma(c2, a, f2mul(ns2, b));
            B[k] = f2fma(s2, a, f2mul(c2,  b));
        }
        da = fmaf(-tt, dot, da);
        db = fmaf( tt, dot, db);
        rot_any = true;
    }
}

__device__ __forceinline__ void norms2(const float2 (&A)[32], const float2 (&B)[32],
                                       float& da, float& db)
{
    float2 na0={0,0}, na1={0,0}, nb0={0,0}, nb1={0,0};
#pragma unroll
    for (int k = 0; k < 32; k += 2) {
        na0 = f2fma(A[k],   A[k],   na0);
        na1 = f2fma(A[k+1], A[k+1], na1);
        nb0 = f2fma(B[k],   B[k],   nb0);
        nb1 = f2fma(B[k+1], B[k+1], nb1);
    }
    da = (na0.x+na0.y)+(na1.x+na1.y);
    db = (nb0.x+nb0.y)+(nb1.x+nb1.y);
}

// One warp per 64x64 SPD matrix. One-sided Jacobi; columns -> lambda_i * u_i.
// Pair schedule: recursive cross-set tournament. Level G (32,16,...,2): G rounds
// pairing lane's A against a B that cycles within the G-lane group (1 SHFL/elem,
// no selects), then regroup via shfl_xor(G/2) splitting A-set/B-set. Level 1:
// local (A,B) rotation. 63 rounds = all 2016 pairs. Column order is scrambled,
// which is harmless: logm = sum_i w_i g_i g_i^T is order-agnostic.
__global__ __launch_bounds__(32, 10)
void logeig_jacobi(const float* __restrict__ X, float* __restrict__ Out, int nmat)
{
    const int lane = threadIdx.x & 31;
    const int mat  = blockIdx.x;

    __shared__ float sh[64 * 68 + 64];

    if (mat >= nmat) return;

    const float* Xm = X + (size_t)mat * 4096;
    float*       Om = Out + (size_t)mat * 4096;

    float2 A[32], B[32];

    // X symmetric: column j == row j (contiguous). Lane holds cols lane, lane+32.
    {
        const float4* rT = reinterpret_cast<const float4*>(Xm + lane * 64);
        const float4* rB = reinterpret_cast<const float4*>(Xm + (lane + 32) * 64);
#pragma unroll
        for (int m = 0; m < 16; m++) {
            float4 a = rT[m];
            A[2*m]   = make_float2(a.x, a.y);
            A[2*m+1] = make_float2(a.z, a.w);
            float4 b = rB[m];
            B[2*m]   = make_float2(b.x, b.y);
            B[2*m+1] = make_float2(b.z, b.w);
        }
    }

    float da, db;

    for (int sweep = 0; sweep < 16; sweep++) {
        norms2(A, B, da, db);           // exact refresh kills incremental drift
        bool rot_any = false;

#pragma unroll 1
        for (int G = 32; G > 1; G >>= 1) {
            const int g   = lane & (G - 1);
            const int src = (lane ^ g) | ((g + 1) & (G - 1));   // next lane in group

#pragma unroll 1
            for (int r = 0; r < G; r++) {
                if (r) {                 // cycle B within group: pure shuffles
#pragma unroll
                    for (int k = 0; k < 32; k++) {
                        float2 v = B[k];
                        v.x = __shfl_sync(WFULL, v.x, src);
                        v.y = __shfl_sync(WFULL, v.y, src);
                        B[k] = v;
                    }
                    db = __shfl_sync(WFULL, db, src);
                }
                rotate_pair(A, B, da, db, rot_any);
            }

            // Regroup: sub-lanes [0,G/2) collect the A-set, [G/2,G) the B-set.
            {
                const int  h  = G >> 1;
                const bool hi = (lane & h) != 0;
#pragma unroll
                for (int k = 0; k < 32; k++) {
                    float2 a = A[k], b = B[k];
                    float sx = hi ? a.x : b.x;
                    float sy = hi ? a.y : b.y;
                    sx = __shfl_xor_sync(WFULL, sx, h);
                    sy = __shfl_xor_sync(WFULL, sy, h);
                    if (hi) A[k] = make_float2(sx, sy);
                    else    B[k] = make_float2(sx, sy);
                }
                float sd = hi ? da : db;
                sd = __shfl_xor_sync(WFULL, sd, h);
                if (hi) da = sd; else db = sd;
            }
        }
        rotate_pair(A, B, da, db, rot_any);   // level G==1: local pair

        if (!__any_sync(WFULL, rot_any)) break;
    }

    // ---- Reconstruction: Out = sum_i w_i g_i g_i^T,  w_i = 0.5*log(d_i)/d_i ----
    norms2(A, B, da, db);                 // exact lambda_i^2

    float* S = sh;                         // S[k*68 + slot] = g_slot[k]
    float* w = sh + 64 * 68;
#pragma unroll
    for (int k = 0; k < 32; k++) {
        S[(2*k  )*68 + lane]      = A[k].x;
        S[(2*k+1)*68 + lane]      = A[k].y;
        S[(2*k  )*68 + lane + 32] = B[k].x;
        S[(2*k+1)*68 + lane + 32] = B[k].y;
    }
    w[lane]      = 0.5f * logf(da) / da;
    w[lane + 32] = 0.5f * logf(db) / db;
    __syncwarp();

    // Reuse A/B registers: A[k] = w.*g[row lane], B[k] = w.*g[row lane+32]
#pragma unroll
    for (int k = 0; k < 32; k++) {
        float2 wk = *reinterpret_cast<const float2*>(w + 2*k);
        float2 g0 = *reinterpret_cast<const float2*>(S + lane*68 + 2*k);
        float2 g1 = *reinterpret_cast<const float2*>(S + (lane+32)*68 + 2*k);
        A[k] = f2mul(wk, g0);
        B[k] = f2mul(wk, g1);
    }

#pragma unroll 1
    for (int c = 0; c < 64; c++) {
        const float2* Sc = reinterpret_cast<const float2*>(S + c*68); // broadcast loads
        float2 s0a={0,0}, s0b={0,0}, s1a={0,0}, s1b={0,0};
#pragma unroll
        for (int k = 0; k < 32; k += 2) {
            float2 g0 = Sc[k], g1 = Sc[k+1];
            s0a = f2fma(A[k],   g0, s0a);
            s0b = f2fma(A[k+1], g1, s0b);
            s1a = f2fma(B[k],   g0, s1a);
            s1b = f2fma(B[k+1], g1, s1b);
        }
        Om[lane*64 + c]        = (s0a.x+s0a.y)+(s0b.x+s0b.y);
        Om[(lane + 32)*64 + c] = (s1a.x+s1a.y)+(s1b.x+s1b.y);
    }
}

extern "C" void kernel_launch(void* const* d_in, const int* in_sizes, int n_in,
                              void* d_out, int out_size)
{
    const float* X  = (const float*)d_in[0];
    float*       Om = (float*)d_out;
    int nmat = in_sizes[0] / 4096;          // 8192 matrices of 64x64
    logeig_jacobi<<<nmat, 32>>>(X, Om, nmat);
}